// round 1
// baseline (speedup 1.0000x reference)
#include <cuda_runtime.h>
#include <cstdint>

// ---------------------------------------------------------------------------
// Vanilla RNN: h_t = tanh(h_{t-1} @ wh + x_t @ wx + b), return final h [B,1,H]
// B=256, T=2048, H=256, all fp32.
//
// Phase 1: xw[b,t,:] = x[b,t,:] @ wx + b      (big parallel GEMM)
// Phase 2: sequential scan over t, batch rows partitioned across CTAs.
// ---------------------------------------------------------------------------

#define B_DIM 256
#define T_DIM 2048
#define H_DIM 256
#define M_TOTAL (B_DIM * T_DIM)   // 524288

// Scratch for the projected inputs (512 MB). Allocation APIs are forbidden;
// use a __device__ global.
__device__ float g_xw[(size_t)M_TOTAL * H_DIM];

// ---------------------------------------------------------------------------
// Projection GEMM: C[M,256] = A[M,256] @ W[256,256] + bias
// Tiles: BM=64, BN=64, BK=16. 256 threads, 4x4 micro-tile per thread.
// ---------------------------------------------------------------------------
#define BM 64
#define BN 64
#define BK 16

__global__ __launch_bounds__(256) void proj_kernel(
    const float* __restrict__ A,      // [M, 256]
    const float* __restrict__ W,      // [256, 256]
    const float* __restrict__ bias,   // [256]
    float* __restrict__ C)            // [M, 256]
{
    __shared__ float As[BK][BM];   // transposed stage: As[k][m]
    __shared__ float Ws[BK][BN];   // Ws[k][n]

    const int t  = threadIdx.x;
    const int n0 = blockIdx.x * BN;
    const long m0 = (long)blockIdx.y * BM;

    // A-tile load indices: 64 rows x 16 k  -> 256 float4 loads
    const int arow = t >> 2;          // 0..63
    const int akq  = (t & 3) * 4;     // 0,4,8,12
    // W-tile load indices: 16 k x 64 n -> 256 float4 loads
    const int wk = t >> 4;            // 0..15
    const int wn = (t & 15) * 4;      // 0..60

    // compute indices
    const int tm = (t >> 4) * 4;      // 0..60
    const int tn = (t & 15) * 4;      // 0..60

    float c[4][4];
#pragma unroll
    for (int i = 0; i < 4; ++i)
#pragma unroll
        for (int j = 0; j < 4; ++j) c[i][j] = 0.0f;

#pragma unroll 1
    for (int kt = 0; kt < H_DIM; kt += BK) {
        // stage A (transposed)
        float4 av = *(const float4*)&A[(m0 + arow) * H_DIM + kt + akq];
        As[akq + 0][arow] = av.x;
        As[akq + 1][arow] = av.y;
        As[akq + 2][arow] = av.z;
        As[akq + 3][arow] = av.w;
        // stage W
        float4 wv = *(const float4*)&W[(long)(kt + wk) * H_DIM + n0 + wn];
        *(float4*)&Ws[wk][wn] = wv;
        __syncthreads();

#pragma unroll
        for (int k = 0; k < BK; ++k) {
            float4 a4 = *(const float4*)&As[k][tm];
            float4 w4 = *(const float4*)&Ws[k][tn];
            float ar[4] = {a4.x, a4.y, a4.z, a4.w};
            float wr[4] = {w4.x, w4.y, w4.z, w4.w};
#pragma unroll
            for (int i = 0; i < 4; ++i)
#pragma unroll
                for (int j = 0; j < 4; ++j)
                    c[i][j] += ar[i] * wr[j];
        }
        __syncthreads();
    }

    float4 bb = *(const float4*)&bias[n0 + tn];
#pragma unroll
    for (int i = 0; i < 4; ++i) {
        float4 o;
        o.x = c[i][0] + bb.x;
        o.y = c[i][1] + bb.y;
        o.z = c[i][2] + bb.z;
        o.w = c[i][3] + bb.w;
        *(float4*)&C[(m0 + tm + i) * H_DIM + n0 + tn] = o;
    }
}

// ---------------------------------------------------------------------------
// Sequential scan. 128 CTAs x 256 threads, 2 batch rows per CTA.
// wh rows [0, SROWS) live in shared memory; the tail rows stream from L2
// (wh is 256 KB and stays L2-resident).
// Thread j owns output column j for both batch rows.
// ---------------------------------------------------------------------------
#define SROWS 224
#define SCAN_SMEM_BYTES (SROWS * H_DIM * 4 + H_DIM * 8)

__global__ __launch_bounds__(256) void scan_kernel(
    const float* __restrict__ xw,   // [B, T, H] (bias already folded in)
    const float* __restrict__ wh,   // [H, H]
    float* __restrict__ out)        // [B, 1, H]
{
    extern __shared__ float sm[];
    float*  ws = sm;                               // [SROWS][256]
    float2* hs = (float2*)(sm + SROWS * H_DIM);    // [256] : (.x=row0, .y=row1)

    const int j  = threadIdx.x;
    const int r0 = blockIdx.x * 2;

    // Stage wh[0:SROWS] into smem (coalesced)
    for (int idx = j; idx < SROWS * H_DIM; idx += 256)
        ws[idx] = wh[idx];
    hs[j] = make_float2(0.0f, 0.0f);
    __syncthreads();

    const float* xw0 = xw + (long)r0 * T_DIM * H_DIM + j;
    const float* xw1 = xw + (long)(r0 + 1) * T_DIM * H_DIM + j;

    float h0 = 0.0f, h1 = 0.0f;

#pragma unroll 1
    for (int tstep = 0; tstep < T_DIM; ++tstep) {
        // Issue the xw loads early; they are consumed ~2000 cycles later.
        float x0 = xw0[(long)tstep * H_DIM];
        float x1 = xw1[(long)tstep * H_DIM];

        float acc0 = 0.0f, acc1 = 0.0f;

#pragma unroll 8
        for (int i = 0; i < SROWS; ++i) {
            float  w = ws[i * H_DIM + j];   // conflict-free: lane j -> bank j
            float2 h = hs[i];               // broadcast
            acc0 += h.x * w;
            acc1 += h.y * w;
        }
#pragma unroll 8
        for (int i = SROWS; i < H_DIM; ++i) {
            float  w = wh[(long)i * H_DIM + j];  // L2-resident tail
            float2 h = hs[i];
            acc0 += h.x * w;
            acc1 += h.y * w;
        }

        acc0 += x0;
        acc1 += x1;
        h0 = tanhf(acc0);
        h1 = tanhf(acc1);

        __syncthreads();                  // all reads of hs done
        hs[j] = make_float2(h0, h1);
        __syncthreads();                  // writes visible before next reads
    }

    out[(long)r0 * H_DIM + j]       = h0;
    out[(long)(r0 + 1) * H_DIM + j] = h1;
}

// ---------------------------------------------------------------------------
// kernel_launch: proj GEMM then scan, both on the default stream (ordered).
// ---------------------------------------------------------------------------
extern "C" void kernel_launch(void* const* d_in, const int* in_sizes, int n_in,
                              void* d_out, int out_size)
{
    const float* x    = (const float*)d_in[0];  // [B, T, H]
    const float* wx   = (const float*)d_in[1];  // [H, H]
    const float* wh   = (const float*)d_in[2];  // [H, H]
    const float* bias = (const float*)d_in[3];  // [1, H]
    float* out = (float*)d_out;                 // [B, 1, H]

    float* xw;
    cudaGetSymbolAddress((void**)&xw, g_xw);

    // Phase 1: xw = x @ wx + bias
    dim3 pgrid(H_DIM / BN, M_TOTAL / BM);   // (4, 8192)
    proj_kernel<<<pgrid, 256>>>(x, wx, bias, xw);

    // Phase 2: sequential scan (needs 226 KB dynamic smem)
    cudaFuncSetAttribute(scan_kernel,
                         cudaFuncAttributeMaxDynamicSharedMemorySize,
                         SCAN_SMEM_BYTES);
    scan_kernel<<<B_DIM / 2, 256, SCAN_SMEM_BYTES>>>(xw, wh, out);
}

// round 2
// speedup vs baseline: 1.6793x; 1.6793x over previous
#include <cuda_runtime.h>
#include <cstdint>

// ---------------------------------------------------------------------------
// Vanilla RNN: h_t = tanh(h_{t-1} @ wh + x_t @ wx + b), return final h [B,1,H]
// B=256, T=2048, H=256, fp32.
// Phase 1: xw = x @ wx + b  (packed-f32x2 tiled GEMM)
// Phase 2: sequential scan, 128 CTAs x 2 batch rows, f32x2 + reg-cached wh.
// ---------------------------------------------------------------------------

#define B_DIM 256
#define T_DIM 2048
#define H_DIM 256
#define M_TOTAL (B_DIM * T_DIM)

typedef unsigned long long u64;

__device__ float g_xw[(size_t)M_TOTAL * H_DIM];   // 512 MB scratch

// ---------------- f32x2 packed helpers (Blackwell FFMA2) -------------------
__device__ __forceinline__ u64 f2fma(u64 a, u64 b, u64 c) {
    u64 d; asm("fma.rn.f32x2 %0,%1,%2,%3;" : "=l"(d) : "l"(a), "l"(b), "l"(c));
    return d;
}
__device__ __forceinline__ u64 f2add(u64 a, u64 b) {
    u64 d; asm("add.rn.f32x2 %0,%1,%2;" : "=l"(d) : "l"(a), "l"(b));
    return d;
}
__device__ __forceinline__ u64 dupf(float x) {
    u64 d; asm("mov.b64 %0,{%1,%1};" : "=l"(d) : "f"(x));
    return d;
}
__device__ __forceinline__ float2 upk(u64 d) {
    float2 v; asm("mov.b64 {%0,%1},%2;" : "=f"(v.x), "=f"(v.y) : "l"(d));
    return v;
}

// ---------------------------------------------------------------------------
// Projection GEMM: C[M,256] = A[M,256] @ W[256,256] + bias
// BM=128, BN=64, BK=16; 256 threads; 8 rows x 4 cols (2 f32x2 pairs) each.
// ---------------------------------------------------------------------------
#define BM 128
#define BN 64
#define BK 16

__global__ __launch_bounds__(256) void proj_kernel(
    const float* __restrict__ A,
    const float* __restrict__ W,
    const float* __restrict__ bias,
    float* __restrict__ C)
{
    __shared__ float As[BK][BM];   // As[k][m]
    __shared__ float Ws[BK][BN];   // Ws[k][n]

    const int t  = threadIdx.x;
    const int n0 = blockIdx.x * BN;
    const long m0 = (long)blockIdx.y * BM;

    // staging indices
    const int arow = t >> 1;           // 0..127
    const int akq  = (t & 1) * 8;      // 0 or 8
    const int wk   = t >> 4;           // 0..15
    const int wn   = (t & 15) * 4;     // 0..60

    // compute indices
    const int tm = (t >> 4) * 8;       // 0..120
    const int tn = (t & 15) * 4;       // 0..60

    u64 acc[8][2];
#pragma unroll
    for (int i = 0; i < 8; ++i) { acc[i][0] = 0ull; acc[i][1] = 0ull; }

#pragma unroll 1
    for (int kt = 0; kt < H_DIM; kt += BK) {
        float4 a0 = *(const float4*)&A[(m0 + arow) * H_DIM + kt + akq];
        float4 a1 = *(const float4*)&A[(m0 + arow) * H_DIM + kt + akq + 4];
        As[akq + 0][arow] = a0.x;  As[akq + 1][arow] = a0.y;
        As[akq + 2][arow] = a0.z;  As[akq + 3][arow] = a0.w;
        As[akq + 4][arow] = a1.x;  As[akq + 5][arow] = a1.y;
        As[akq + 6][arow] = a1.z;  As[akq + 7][arow] = a1.w;
        *(float4*)&Ws[wk][wn] =
            *(const float4*)&W[(long)(kt + wk) * H_DIM + n0 + wn];
        __syncthreads();

#pragma unroll
        for (int k = 0; k < BK; ++k) {
            float4 av0 = *(const float4*)&As[k][tm];
            float4 av1 = *(const float4*)&As[k][tm + 4];
            u64 w01 = *(const u64*)&Ws[k][tn];
            u64 w23 = *(const u64*)&Ws[k][tn + 2];
            float ar[8] = {av0.x, av0.y, av0.z, av0.w,
                           av1.x, av1.y, av1.z, av1.w};
#pragma unroll
            for (int i = 0; i < 8; ++i) {
                u64 ad = dupf(ar[i]);
                acc[i][0] = f2fma(ad, w01, acc[i][0]);
                acc[i][1] = f2fma(ad, w23, acc[i][1]);
            }
        }
        __syncthreads();
    }

    u64 bb01 = *(const u64*)&bias[n0 + tn];
    u64 bb23 = *(const u64*)&bias[n0 + tn + 2];
#pragma unroll
    for (int i = 0; i < 8; ++i) {
        float2 r01 = upk(f2add(acc[i][0], bb01));
        float2 r23 = upk(f2add(acc[i][1], bb23));
        float4 o = make_float4(r01.x, r01.y, r23.x, r23.y);
        *(float4*)&C[(m0 + tm + i) * H_DIM + n0 + tn] = o;
    }
}

// ---------------------------------------------------------------------------
// Scan v2. 128 CTAs x 512 threads, 2 batch rows per CTA.
// Thread (kg in [0,16), p8 in [0,32)): k-range of 16 (8 from regs, 8 from
// smem), 8 columns = 4 f32x2 column-pairs, both batch rows.
// h kept in smem PRE-DUPLICATED per row: hd_r[k] = (h_r[k], h_r[k]).
// Per step: partial accumulation -> STS partials -> bar -> 256-thread packed
// reduction + tanh + hd update -> bar.
// ---------------------------------------------------------------------------
#define KG 16
#define PG 32
#define K_PER 16           // 256 / KG
#define REG_K 8
#define SMEM_K 8
#define SCAN_THREADS 512
#define PADCP 160          // padded col-pair stride in partials

// smem layout (u64 units):
//   wsm : KG*SMEM_K*128 = 16384   (128 KB)  w col-pairs, smem-resident half
//   hd0 : 256                     (2 KB)    (h0,h0) per column
//   hd1 : 256                     (2 KB)    (h1,h1) per column
//   sp0 : KG*PADCP = 2560         (20 KB)   row-0 partials
//   sp1 : 2560                    (20 KB)   row-1 partials
#define WSM_U64 (KG * SMEM_K * 128)
#define SCAN_SMEM_U64 (WSM_U64 + 256 + 256 + KG * PADCP * 2)
#define SCAN_SMEM_BYTES (SCAN_SMEM_U64 * 8)

__global__ __launch_bounds__(SCAN_THREADS, 1) void scan_kernel(
    const float* __restrict__ xw,   // [B, T, H]
    const float* __restrict__ wh,   // [H, H]
    float* __restrict__ out)        // [B, 1, H]
{
    extern __shared__ u64 sm[];
    u64* wsm = sm;
    u64* hd0 = sm + WSM_U64;
    u64* hd1 = hd0 + 256;
    u64* sp0 = hd1 + 256;
    u64* sp1 = sp0 + KG * PADCP;

    const int tid = threadIdx.x;
    const int kg  = tid >> 5;       // 0..15
    const int p8  = tid & 31;       // 0..31
    const int r0  = blockIdx.x * 2;

    const u64* whd = (const u64*)wh;      // wh as col-pairs [256][128]

    // ---- stage smem half of wh: k in [kg2*16+8, kg2*16+16) ----
    for (int e = tid; e < WSM_U64; e += SCAN_THREADS) {
        int kgs = e >> 10;               // 0..15
        int kk  = (e >> 7) & 7;          // 0..7
        int cpx = e & 127;               // col-pair
        int k   = kgs * K_PER + REG_K + kk;
        wsm[e] = whd[k * 128 + cpx];
    }
    if (tid < 256) { hd0[tid] = 0ull; hd1[tid] = 0ull; }

    // ---- register-cache the other half: k in [kg*16, kg*16+8) ----
    u64 wr[REG_K][4];
    const int cpb = p8 * 4;              // first col-pair of this thread
    const int kb  = kg * K_PER;
#pragma unroll
    for (int kk = 0; kk < REG_K; ++kk) {
#pragma unroll
        for (int ci = 0; ci < 4; ++ci)
            wr[kk][ci] = whd[(kb + kk) * 128 + cpb + ci];
    }
    __syncthreads();

    // reduce-thread mapping
    const int rr = tid >> 7;             // 0..3 (only rr<2 used)
    const int cp = tid & 127;
    const u64* xwrow = (tid < 256)
        ? (const u64*)xw + ((long)(r0 + rr) * T_DIM) * 128 + cp
        : (const u64*)xw;

    const u64* wsm_t = wsm + kg * (SMEM_K * 128) + cpb;
    const u64* hd0_t = hd0 + kb;
    const u64* hd1_t = hd1 + kb;
    u64* sp0_t = sp0 + kg * PADCP + p8 * 5;   // p8*5 == cp + (cp>>2) base
    u64* sp1_t = sp1 + kg * PADCP + p8 * 5;
    const int rdoff = cp + (cp >> 2);
    const u64* sprd = (rr == 0) ? sp0 : sp1;
    u64* hdw = (rr == 0) ? hd0 : hd1;

#pragma unroll 1
    for (int t = 0; t < T_DIM; ++t) {
        // prefetch xw for this step's reduction (used ~1k cycles later)
        u64 xv = 0ull;
        if (tid < 256) xv = xwrow[(long)t * 128];

        u64 a00 = 0, a01 = 0, a02 = 0, a03 = 0;
        u64 a10 = 0, a11 = 0, a12 = 0, a13 = 0;

        // ---- register half ----
#pragma unroll
        for (int kk = 0; kk < REG_K; ++kk) {
            u64 h0 = hd0_t[kk];
            u64 h1 = hd1_t[kk];
            a00 = f2fma(h0, wr[kk][0], a00);
            a01 = f2fma(h0, wr[kk][1], a01);
            a02 = f2fma(h0, wr[kk][2], a02);
            a03 = f2fma(h0, wr[kk][3], a03);
            a10 = f2fma(h1, wr[kk][0], a10);
            a11 = f2fma(h1, wr[kk][1], a11);
            a12 = f2fma(h1, wr[kk][2], a12);
            a13 = f2fma(h1, wr[kk][3], a13);
        }
        // ---- smem half ----
#pragma unroll
        for (int kk = 0; kk < SMEM_K; ++kk) {
            u64 h0 = hd0_t[REG_K + kk];
            u64 h1 = hd1_t[REG_K + kk];
            ulonglong2 wa = *(const ulonglong2*)&wsm_t[kk * 128];
            ulonglong2 wb = *(const ulonglong2*)&wsm_t[kk * 128 + 2];
            a00 = f2fma(h0, wa.x, a00);
            a01 = f2fma(h0, wa.y, a01);
            a02 = f2fma(h0, wb.x, a02);
            a03 = f2fma(h0, wb.y, a03);
            a10 = f2fma(h1, wa.x, a10);
            a11 = f2fma(h1, wa.y, a11);
            a12 = f2fma(h1, wb.x, a12);
            a13 = f2fma(h1, wb.y, a13);
        }

        // ---- partials (padded layout: 2-way conflicts max) ----
        sp0_t[0] = a00;  sp0_t[1] = a01;  sp0_t[2] = a02;  sp0_t[3] = a03;
        sp1_t[0] = a10;  sp1_t[1] = a11;  sp1_t[2] = a12;  sp1_t[3] = a13;
        __syncthreads();

        // ---- reduction: 256 threads, one column-pair x one row each ----
        if (tid < 256) {
            u64 s = sprd[rdoff];
#pragma unroll
            for (int g = 1; g < KG; ++g)
                s = f2add(s, sprd[g * PADCP + rdoff]);
            s = f2add(s, xv);
            float2 sv = upk(s);
            float v0 = tanhf(sv.x);
            float v1 = tanhf(sv.y);
            hdw[2 * cp]     = dupf(v0);
            hdw[2 * cp + 1] = dupf(v1);
            if (t == T_DIM - 1)
                *(float2*)&out[(long)(r0 + rr) * H_DIM + 2 * cp] =
                    make_float2(v0, v1);
        }
        __syncthreads();
    }
}

// ---------------------------------------------------------------------------
extern "C" void kernel_launch(void* const* d_in, const int* in_sizes, int n_in,
                              void* d_out, int out_size)
{
    const float* x    = (const float*)d_in[0];
    const float* wx   = (const float*)d_in[1];
    const float* wh   = (const float*)d_in[2];
    const float* bias = (const float*)d_in[3];
    float* out = (float*)d_out;

    float* xw;
    cudaGetSymbolAddress((void**)&xw, g_xw);

    dim3 pgrid(H_DIM / BN, M_TOTAL / BM);   // (4, 4096)
    proj_kernel<<<pgrid, 256>>>(x, wx, bias, xw);

    cudaFuncSetAttribute(scan_kernel,
                         cudaFuncAttributeMaxDynamicSharedMemorySize,
                         SCAN_SMEM_BYTES);
    scan_kernel<<<B_DIM / 2, SCAN_THREADS, SCAN_SMEM_BYTES>>>(xw, wh, out);
}

// round 5
// speedup vs baseline: 1.9353x; 1.1525x over previous
#include <cuda_runtime.h>
#include <cuda_bf16.h>
#include <cstdint>

// ---------------------------------------------------------------------------
// Vanilla RNN: h_t = tanh(h_{t-1} @ wh + x_t @ wx + b), out = h_T  [B,1,H]
// B=256, T=2048, H=256 fp32.
// Phase 0: prep — transpose+split wx into bf16 hi/lo
// Phase 1: proj — xw = x @ wx + b via mma.sync bf16x3 (error-compensated)
//                 (tcgen05 is unavailable: harness targets sm_100, not sm_100a)
// Phase 2: scan — sequential recurrence, f32x2 + reg/smem-cached wh
// ---------------------------------------------------------------------------

#define B_DIM 256
#define T_DIM 2048
#define H_DIM 256
#define M_TOTAL (B_DIM * T_DIM)

typedef unsigned long long u64;

__device__ float g_xw[(size_t)M_TOTAL * H_DIM];          // 512 MB scratch
__device__ __nv_bfloat16 g_wT_hi[H_DIM * H_DIM];         // wx^T hi (bf16), [n][k]
__device__ __nv_bfloat16 g_wT_lo[H_DIM * H_DIM];         // wx^T lo (bf16), [n][k]

// ------------------------- packed f32x2 helpers -----------------------------
__device__ __forceinline__ u64 f2fma(u64 a, u64 b, u64 c) {
    u64 d; asm("fma.rn.f32x2 %0,%1,%2,%3;" : "=l"(d) : "l"(a), "l"(b), "l"(c));
    return d;
}
__device__ __forceinline__ u64 f2add(u64 a, u64 b) {
    u64 d; asm("add.rn.f32x2 %0,%1,%2;" : "=l"(d) : "l"(a), "l"(b));
    return d;
}
__device__ __forceinline__ u64 dupf(float x) {
    u64 d; asm("mov.b64 %0,{%1,%1};" : "=l"(d) : "f"(x));
    return d;
}
__device__ __forceinline__ float2 upk(u64 d) {
    float2 v; asm("mov.b64 {%0,%1},%2;" : "=f"(v.x), "=f"(v.y) : "l"(d));
    return v;
}

// ------------------------- mma.sync helpers (sm_80+ PTX) -------------------
__device__ __forceinline__ uint32_t smem_u32(const void* p) {
    uint32_t a;
    asm("{ .reg .u64 t; cvta.to.shared.u64 t, %1; cvt.u32.u64 %0, t; }"
        : "=r"(a) : "l"(p));
    return a;
}
__device__ __forceinline__ void ldsm_x4(uint32_t* r, uint32_t addr) {
    asm volatile("ldmatrix.sync.aligned.m8n8.x4.shared.b16 {%0,%1,%2,%3}, [%4];"
                 : "=r"(r[0]), "=r"(r[1]), "=r"(r[2]), "=r"(r[3]) : "r"(addr));
}
__device__ __forceinline__ void mma_bf16(float* d, const uint32_t* a,
                                         const uint32_t* b) {
    asm volatile(
        "mma.sync.aligned.m16n8k16.row.col.f32.bf16.bf16.f32 "
        "{%0,%1,%2,%3},{%4,%5,%6,%7},{%8,%9},{%0,%1,%2,%3};"
        : "+f"(d[0]), "+f"(d[1]), "+f"(d[2]), "+f"(d[3])
        : "r"(a[0]), "r"(a[1]), "r"(a[2]), "r"(a[3]), "r"(b[0]), "r"(b[1]));
}

// ---------------------------------------------------------------------------
// Prep: g_wT_{hi,lo}[n][k] = bf16 split of wx[k][n]
// ---------------------------------------------------------------------------
__global__ void prep_kernel(const float* __restrict__ wx) {
    int k = blockIdx.x;
    int n = threadIdx.x;
    float v = wx[k * H_DIM + n];
    __nv_bfloat16 hi = __float2bfloat16(v);
    __nv_bfloat16 lo = __float2bfloat16(v - __bfloat162float(hi));
    g_wT_hi[n * H_DIM + k] = hi;
    g_wT_lo[n * H_DIM + k] = lo;
}

// ---------------------------------------------------------------------------
// Proj: xw[m,n] = sum_k x[m,k] wx[k,n] + b[n] via mma.sync bf16x3.
// CTA: 128x128 tile, 256 threads (8 warps, each 32x64), K chunk = 64.
// smem row stride 72 bf16 = 144 B (16B-aligned, conflict-free for ldmatrix).
// ---------------------------------------------------------------------------
#define PM 128
#define PN 128
#define PBK 64
#define LDA_B 144                       // bytes per smem row (72 bf16)

#define SA_HI 0
#define SA_LO (SA_HI + PM * LDA_B)      // 18432
#define SW_HI (SA_LO + PM * LDA_B)      // 36864
#define SW_LO (SW_HI + PN * LDA_B)      // 55296
#define SBIAS (SW_LO + PN * LDA_B)      // 73728
#define PS_TOTAL (SBIAS + PN * 4)       // 74240

__global__ __launch_bounds__(256) void proj_kernel(
    const float* __restrict__ x,
    const float* __restrict__ bias)
{
    extern __shared__ __align__(128) char sm[];
    const uint32_t smb = smem_u32(sm);
    const int tid  = threadIdx.x;
    const int wid  = tid >> 5;
    const int lane = tid & 31;
    const int n0 = blockIdx.x * PN;
    const long m0 = (long)blockIdx.y * PM;
    const int wm = (wid >> 1) * 32;     // warp m-base within tile
    const int wn = (wid & 1) * 64;      // warp n-base within tile

    if (tid < PN) ((float*)(sm + SBIAS))[tid] = bias[n0 + tid];

    float d[2][8][4];
#pragma unroll
    for (int mt = 0; mt < 2; ++mt)
#pragma unroll
        for (int nt = 0; nt < 8; ++nt)
#pragma unroll
            for (int i = 0; i < 4; ++i) d[mt][nt][i] = 0.0f;

    // staging indices
    const int srow = tid >> 1;          // 0..127
    const int sc0  = (tid & 1) * 32;    // 0 or 32 (bf16 cols)

    // ldmatrix address components
    const int a_row = lane & 15;
    const int a_c8  = (lane >> 4) * 8;
    const int b_sel = lane >> 3;                        // 0..3
    const int b_nof = (b_sel >> 1) * 8 + (lane & 7);    // row within 16-n group
    const int b_kof = (b_sel & 1) * 8;

#pragma unroll 1
    for (int kc = 0; kc < H_DIM / PBK; ++kc) {
        const int k0 = kc * PBK;
        __syncthreads();   // previous iteration's reads done

        // ---- stage A chunk: fp32 -> bf16 hi/lo ----
        {
            const float4* src = (const float4*)(x + (m0 + srow) * H_DIM + k0 + sc0);
            __nv_bfloat162* dhi =
                (__nv_bfloat162*)(sm + SA_HI + srow * LDA_B + sc0 * 2);
            __nv_bfloat162* dlo =
                (__nv_bfloat162*)(sm + SA_LO + srow * LDA_B + sc0 * 2);
#pragma unroll
            for (int q = 0; q < 8; ++q) {
                float4 v = src[q];
                __nv_bfloat16 h0 = __float2bfloat16(v.x);
                __nv_bfloat16 h1 = __float2bfloat16(v.y);
                __nv_bfloat16 h2 = __float2bfloat16(v.z);
                __nv_bfloat16 h3 = __float2bfloat16(v.w);
                __nv_bfloat16 l0 = __float2bfloat16(v.x - __bfloat162float(h0));
                __nv_bfloat16 l1 = __float2bfloat16(v.y - __bfloat162float(h1));
                __nv_bfloat16 l2 = __float2bfloat16(v.z - __bfloat162float(h2));
                __nv_bfloat16 l3 = __float2bfloat16(v.w - __bfloat162float(h3));
                dhi[q * 2]     = __nv_bfloat162{h0, h1};
                dhi[q * 2 + 1] = __nv_bfloat162{h2, h3};
                dlo[q * 2]     = __nv_bfloat162{l0, l1};
                dlo[q * 2 + 1] = __nv_bfloat162{l2, l3};
            }
        }
        // ---- stage W chunk (already bf16 hi/lo, [n][k]) ----
        {
            const uint4* shi = (const uint4*)(g_wT_hi + (n0 + srow) * H_DIM + k0 + sc0);
            const uint4* slo = (const uint4*)(g_wT_lo + (n0 + srow) * H_DIM + k0 + sc0);
            uint4* dhi = (uint4*)(sm + SW_HI + srow * LDA_B + sc0 * 2);
            uint4* dlo = (uint4*)(sm + SW_LO + srow * LDA_B + sc0 * 2);
#pragma unroll
            for (int q = 0; q < 4; ++q) { dhi[q] = shi[q]; dlo[q] = slo[q]; }
        }
        __syncthreads();

        // ---- compute: 4 k16 steps ----
#pragma unroll
        for (int kk = 0; kk < 4; ++kk) {
            const int kb = kk * 16;
            uint32_t ahi[2][4], alo[2][4], bfr[8][2];

#pragma unroll
            for (int mt = 0; mt < 2; ++mt) {
                uint32_t ra = (wm + mt * 16 + a_row) * LDA_B + (kb + a_c8) * 2;
                ldsm_x4(ahi[mt], smb + SA_HI + ra);
                ldsm_x4(alo[mt], smb + SA_LO + ra);
            }
            // B_hi fragments (2 n-tiles per x4)
#pragma unroll
            for (int ntp = 0; ntp < 4; ++ntp) {
                uint32_t rb = (wn + ntp * 16 + b_nof) * LDA_B + (kb + b_kof) * 2;
                uint32_t r[4];
                ldsm_x4(r, smb + SW_HI + rb);
                bfr[ntp * 2][0] = r[0];  bfr[ntp * 2][1] = r[1];
                bfr[ntp * 2 + 1][0] = r[2];  bfr[ntp * 2 + 1][1] = r[3];
            }
#pragma unroll
            for (int mt = 0; mt < 2; ++mt)
#pragma unroll
                for (int nt = 0; nt < 8; ++nt) {
                    mma_bf16(d[mt][nt], ahi[mt], bfr[nt]);   // A_hi * B_hi
                    mma_bf16(d[mt][nt], alo[mt], bfr[nt]);   // A_lo * B_hi
                }
            // B_lo fragments
#pragma unroll
            for (int ntp = 0; ntp < 4; ++ntp) {
                uint32_t rb = (wn + ntp * 16 + b_nof) * LDA_B + (kb + b_kof) * 2;
                uint32_t r[4];
                ldsm_x4(r, smb + SW_LO + rb);
                bfr[ntp * 2][0] = r[0];  bfr[ntp * 2][1] = r[1];
                bfr[ntp * 2 + 1][0] = r[2];  bfr[ntp * 2 + 1][1] = r[3];
            }
#pragma unroll
            for (int mt = 0; mt < 2; ++mt)
#pragma unroll
                for (int nt = 0; nt < 8; ++nt)
                    mma_bf16(d[mt][nt], ahi[mt], bfr[nt]);   // A_hi * B_lo
        }
    }

    // ---- epilogue: + bias, write fp32 ----
    const float* sbias = (const float*)(sm + SBIAS);
    const int g  = lane >> 2;
    const int tc = lane & 3;
#pragma unroll
    for (int mt = 0; mt < 2; ++mt) {
        long r = m0 + wm + mt * 16 + g;
#pragma unroll
        for (int nt = 0; nt < 8; ++nt) {
            int cn = wn + nt * 8 + tc * 2;
            float b0 = sbias[cn], b1 = sbias[cn + 1];
            *(float2*)&g_xw[r * H_DIM + n0 + cn] =
                make_float2(d[mt][nt][0] + b0, d[mt][nt][1] + b1);
            *(float2*)&g_xw[(r + 8) * H_DIM + n0 + cn] =
                make_float2(d[mt][nt][2] + b0, d[mt][nt][3] + b1);
        }
    }
}

// ---------------------------------------------------------------------------
// Scan. 128 CTAs x 512 threads, 2 batch rows per CTA. f32x2 everywhere.
// Thread (kg, p8): k-range 16 (8 reg-cached, 8 smem), 4 col-pairs, 2 rows.
// ---------------------------------------------------------------------------
#define KG 16
#define K_PER 16
#define REG_K 8
#define SMEM_K 8
#define SCAN_THREADS 512

#define WSM_U64 (KG * SMEM_K * 128)
#define SCAN_SMEM_U64 (WSM_U64 + 256 + 256 + KG * 128 * 2)
#define SCAN_SMEM_BYTES (SCAN_SMEM_U64 * 8)

__global__ __launch_bounds__(SCAN_THREADS, 1) void scan_kernel(
    const float* __restrict__ xw,
    const float* __restrict__ wh,
    float* __restrict__ out)
{
    extern __shared__ __align__(1024) u64 smu[];
    u64* wsm = smu;
    u64* hd0 = smu + WSM_U64;
    u64* hd1 = hd0 + 256;
    u64* sp0 = hd1 + 256;
    u64* sp1 = sp0 + KG * 128;

    const int tid = threadIdx.x;
    const int kg  = tid >> 5;
    const int p8  = tid & 31;
    const int r0  = blockIdx.x * 2;

    const u64* whd = (const u64*)wh;

    for (int e = tid; e < WSM_U64; e += SCAN_THREADS) {
        int kgs = e >> 10;
        int kk  = (e >> 7) & 7;
        int cpx = e & 127;
        wsm[e] = whd[(kgs * K_PER + REG_K + kk) * 128 + cpx];
    }
    if (tid < 256) { hd0[tid] = 0ull; hd1[tid] = 0ull; }

    u64 wr[REG_K][4];
    const int cpb = p8 * 4;
    const int kb  = kg * K_PER;
#pragma unroll
    for (int kk = 0; kk < REG_K; ++kk)
#pragma unroll
        for (int ci = 0; ci < 4; ++ci)
            wr[kk][ci] = whd[(kb + kk) * 128 + cpb + ci];
    __syncthreads();

    const int rr = tid >> 7;
    const int cp = tid & 127;
    const u64* xwrow = (tid < 256)
        ? (const u64*)xw + ((long)(r0 + rr) * T_DIM) * 128 + cp
        : (const u64*)xw;

    const u64* wsm_t = wsm + kg * (SMEM_K * 128) + cpb;
    const u64* hd0_t = hd0 + kb;
    const u64* hd1_t = hd1 + kb;
    ulonglong2* sp0_t = (ulonglong2*)(sp0 + kg * 128 + cpb);
    ulonglong2* sp1_t = (ulonglong2*)(sp1 + kg * 128 + cpb);
    const u64* sprd = (rr == 0) ? sp0 : sp1;
    u64* hdw = (rr == 0) ? hd0 : hd1;

#pragma unroll 1
    for (int t = 0; t < T_DIM; ++t) {
        u64 xv = 0ull;
        if (tid < 256) xv = xwrow[(long)t * 128];

        u64 a00 = 0, a01 = 0, a02 = 0, a03 = 0;
        u64 a10 = 0, a11 = 0, a12 = 0, a13 = 0;

#pragma unroll
        for (int kk = 0; kk < REG_K; kk += 2) {
            ulonglong2 h0p = *(const ulonglong2*)&hd0_t[kk];
            ulonglong2 h1p = *(const ulonglong2*)&hd1_t[kk];
            a00 = f2fma(h0p.x, wr[kk][0], a00);
            a01 = f2fma(h0p.x, wr[kk][1], a01);
            a02 = f2fma(h0p.x, wr[kk][2], a02);
            a03 = f2fma(h0p.x, wr[kk][3], a03);
            a10 = f2fma(h1p.x, wr[kk][0], a10);
            a11 = f2fma(h1p.x, wr[kk][1], a11);
            a12 = f2fma(h1p.x, wr[kk][2], a12);
            a13 = f2fma(h1p.x, wr[kk][3], a13);
            a00 = f2fma(h0p.y, wr[kk + 1][0], a00);
            a01 = f2fma(h0p.y, wr[kk + 1][1], a01);
            a02 = f2fma(h0p.y, wr[kk + 1][2], a02);
            a03 = f2fma(h0p.y, wr[kk + 1][3], a03);
            a10 = f2fma(h1p.y, wr[kk + 1][0], a10);
            a11 = f2fma(h1p.y, wr[kk + 1][1], a11);
            a12 = f2fma(h1p.y, wr[kk + 1][2], a12);
            a13 = f2fma(h1p.y, wr[kk + 1][3], a13);
        }
#pragma unroll
        for (int kk = 0; kk < SMEM_K; kk += 2) {
            ulonglong2 h0p = *(const ulonglong2*)&hd0_t[REG_K + kk];
            ulonglong2 h1p = *(const ulonglong2*)&hd1_t[REG_K + kk];
            ulonglong2 wa0 = *(const ulonglong2*)&wsm_t[kk * 128];
            ulonglong2 wb0 = *(const ulonglong2*)&wsm_t[kk * 128 + 2];
            ulonglong2 wa1 = *(const ulonglong2*)&wsm_t[(kk + 1) * 128];
            ulonglong2 wb1 = *(const ulonglong2*)&wsm_t[(kk + 1) * 128 + 2];
            a00 = f2fma(h0p.x, wa0.x, a00);
            a01 = f2fma(h0p.x, wa0.y, a01);
            a02 = f2fma(h0p.x, wb0.x, a02);
            a03 = f2fma(h0p.x, wb0.y, a03);
            a10 = f2fma(h1p.x, wa0.x, a10);
            a11 = f2fma(h1p.x, wa0.y, a11);
            a12 = f2fma(h1p.x, wb0.x, a12);
            a13 = f2fma(h1p.x, wb0.y, a13);
            a00 = f2fma(h0p.y, wa1.x, a00);
            a01 = f2fma(h0p.y, wa1.y, a01);
            a02 = f2fma(h0p.y, wb1.x, a02);
            a03 = f2fma(h0p.y, wb1.y, a03);
            a10 = f2fma(h1p.y, wa1.x, a10);
            a11 = f2fma(h1p.y, wa1.y, a11);
            a12 = f2fma(h1p.y, wb1.x, a12);
            a13 = f2fma(h1p.y, wb1.y, a13);
        }

        sp0_t[0] = make_ulonglong2(a00, a01);
        sp0_t[1] = make_ulonglong2(a02, a03);
        sp1_t[0] = make_ulonglong2(a10, a11);
        sp1_t[1] = make_ulonglong2(a12, a13);
        __syncthreads();

        if (tid < 256) {
            u64 s = sprd[cp];
#pragma unroll
            for (int g = 1; g < KG; ++g)
                s = f2add(s, sprd[g * 128 + cp]);
            s = f2add(s, xv);
            float2 sv = upk(s);
            float v0 = tanhf(sv.x);
            float v1 = tanhf(sv.y);
            *(ulonglong2*)&hdw[2 * cp] = make_ulonglong2(dupf(v0), dupf(v1));
            if (t == T_DIM - 1)
                *(float2*)&out[(long)(r0 + rr) * H_DIM + 2 * cp] =
                    make_float2(v0, v1);
        }
        __syncthreads();
    }
}

// ---------------------------------------------------------------------------
extern "C" void kernel_launch(void* const* d_in, const int* in_sizes, int n_in,
                              void* d_out, int out_size)
{
    const float* x    = (const float*)d_in[0];
    const float* wx   = (const float*)d_in[1];
    const float* wh   = (const float*)d_in[2];
    const float* bias = (const float*)d_in[3];
    float* out = (float*)d_out;

    float* xw;
    cudaGetSymbolAddress((void**)&xw, g_xw);

    prep_kernel<<<H_DIM, H_DIM>>>(wx);

    cudaFuncSetAttribute(proj_kernel,
                         cudaFuncAttributeMaxDynamicSharedMemorySize, PS_TOTAL);
    dim3 pgrid(H_DIM / PN, M_TOTAL / PM);   // (2, 4096)
    proj_kernel<<<pgrid, 256, PS_TOTAL>>>(x, bias);

    cudaFuncSetAttribute(scan_kernel,
                         cudaFuncAttributeMaxDynamicSharedMemorySize,
                         SCAN_SMEM_BYTES);
    scan_kernel<<<B_DIM / 2, SCAN_THREADS, SCAN_SMEM_BYTES>>>(xw, wh, out);
}

// round 6
// speedup vs baseline: 2.4629x; 1.2726x over previous
#include <cuda_runtime.h>
#include <cuda_bf16.h>
#include <cstdint>

// ---------------------------------------------------------------------------
// Vanilla RNN: h_t = tanh(h_{t-1} @ wh + x_t @ wx + b), out = h_T  [B,1,H]
// B=256, T=2048, H=256 fp32.
// Phase 0: prep — transpose+split wx into bf16 hi/lo
// Phase 1: proj — xw = x @ wx + b via mma.sync bf16x3 (error-compensated)
// Phase 2: scan — sequential recurrence; dense-plane smem layout so every
//                 LDS.128/STS.128 wavefront moves a full 128B segment.
// ---------------------------------------------------------------------------

#define B_DIM 256
#define T_DIM 2048
#define H_DIM 256
#define M_TOTAL (B_DIM * T_DIM)

typedef unsigned long long u64;

__device__ float g_xw[(size_t)M_TOTAL * H_DIM];          // 512 MB scratch
__device__ __nv_bfloat16 g_wT_hi[H_DIM * H_DIM];         // wx^T hi (bf16), [n][k]
__device__ __nv_bfloat16 g_wT_lo[H_DIM * H_DIM];         // wx^T lo (bf16), [n][k]

// ------------------------- packed f32x2 helpers -----------------------------
__device__ __forceinline__ u64 f2fma(u64 a, u64 b, u64 c) {
    u64 d; asm("fma.rn.f32x2 %0,%1,%2,%3;" : "=l"(d) : "l"(a), "l"(b), "l"(c));
    return d;
}
__device__ __forceinline__ u64 f2add(u64 a, u64 b) {
    u64 d; asm("add.rn.f32x2 %0,%1,%2;" : "=l"(d) : "l"(a), "l"(b));
    return d;
}
__device__ __forceinline__ u64 dupf(float x) {
    u64 d; asm("mov.b64 %0,{%1,%1};" : "=l"(d) : "f"(x));
    return d;
}
__device__ __forceinline__ float2 upk(u64 d) {
    float2 v; asm("mov.b64 {%0,%1},%2;" : "=f"(v.x), "=f"(v.y) : "l"(d));
    return v;
}

// ------------------------- mma.sync helpers (sm_80+ PTX) -------------------
__device__ __forceinline__ uint32_t smem_u32(const void* p) {
    uint32_t a;
    asm("{ .reg .u64 t; cvta.to.shared.u64 t, %1; cvt.u32.u64 %0, t; }"
        : "=r"(a) : "l"(p));
    return a;
}
__device__ __forceinline__ void ldsm_x4(uint32_t* r, uint32_t addr) {
    asm volatile("ldmatrix.sync.aligned.m8n8.x4.shared.b16 {%0,%1,%2,%3}, [%4];"
                 : "=r"(r[0]), "=r"(r[1]), "=r"(r[2]), "=r"(r[3]) : "r"(addr));
}
__device__ __forceinline__ void mma_bf16(float* d, const uint32_t* a,
                                         const uint32_t* b) {
    asm volatile(
        "mma.sync.aligned.m16n8k16.row.col.f32.bf16.bf16.f32 "
        "{%0,%1,%2,%3},{%4,%5,%6,%7},{%8,%9},{%0,%1,%2,%3};"
        : "+f"(d[0]), "+f"(d[1]), "+f"(d[2]), "+f"(d[3])
        : "r"(a[0]), "r"(a[1]), "r"(a[2]), "r"(a[3]), "r"(b[0]), "r"(b[1]));
}

// ---------------------------------------------------------------------------
// Prep: g_wT_{hi,lo}[n][k] = bf16 split of wx[k][n]
// ---------------------------------------------------------------------------
__global__ void prep_kernel(const float* __restrict__ wx) {
    int k = blockIdx.x;
    int n = threadIdx.x;
    float v = wx[k * H_DIM + n];
    __nv_bfloat16 hi = __float2bfloat16(v);
    __nv_bfloat16 lo = __float2bfloat16(v - __bfloat162float(hi));
    g_wT_hi[n * H_DIM + k] = hi;
    g_wT_lo[n * H_DIM + k] = lo;
}

// ---------------------------------------------------------------------------
// Proj: xw[m,n] = sum_k x[m,k] wx[k,n] + b[n] via mma.sync bf16x3.
// CTA: 128x128 tile, 256 threads (8 warps, each 32x64), K chunk = 64.
// ---------------------------------------------------------------------------
#define PM 128
#define PN 128
#define PBK 64
#define LDA_B 144                       // bytes per smem row (72 bf16)

#define SA_HI 0
#define SA_LO (SA_HI + PM * LDA_B)
#define SW_HI (SA_LO + PM * LDA_B)
#define SW_LO (SW_HI + PN * LDA_B)
#define SBIAS (SW_LO + PN * LDA_B)
#define PS_TOTAL (SBIAS + PN * 4)

__global__ __launch_bounds__(256) void proj_kernel(
    const float* __restrict__ x,
    const float* __restrict__ bias)
{
    extern __shared__ __align__(128) char sm[];
    const uint32_t smb = smem_u32(sm);
    const int tid  = threadIdx.x;
    const int wid  = tid >> 5;
    const int lane = tid & 31;
    const int n0 = blockIdx.x * PN;
    const long m0 = (long)blockIdx.y * PM;
    const int wm = (wid >> 1) * 32;
    const int wn = (wid & 1) * 64;

    if (tid < PN) ((float*)(sm + SBIAS))[tid] = bias[n0 + tid];

    float d[2][8][4];
#pragma unroll
    for (int mt = 0; mt < 2; ++mt)
#pragma unroll
        for (int nt = 0; nt < 8; ++nt)
#pragma unroll
            for (int i = 0; i < 4; ++i) d[mt][nt][i] = 0.0f;

    const int srow = tid >> 1;
    const int sc0  = (tid & 1) * 32;

    const int a_row = lane & 15;
    const int a_c8  = (lane >> 4) * 8;
    const int b_sel = lane >> 3;
    const int b_nof = (b_sel >> 1) * 8 + (lane & 7);
    const int b_kof = (b_sel & 1) * 8;

#pragma unroll 1
    for (int kc = 0; kc < H_DIM / PBK; ++kc) {
        const int k0 = kc * PBK;
        __syncthreads();

        {
            const float4* src = (const float4*)(x + (m0 + srow) * H_DIM + k0 + sc0);
            __nv_bfloat162* dhi =
                (__nv_bfloat162*)(sm + SA_HI + srow * LDA_B + sc0 * 2);
            __nv_bfloat162* dlo =
                (__nv_bfloat162*)(sm + SA_LO + srow * LDA_B + sc0 * 2);
#pragma unroll
            for (int q = 0; q < 8; ++q) {
                float4 v = src[q];
                __nv_bfloat16 h0 = __float2bfloat16(v.x);
                __nv_bfloat16 h1 = __float2bfloat16(v.y);
                __nv_bfloat16 h2 = __float2bfloat16(v.z);
                __nv_bfloat16 h3 = __float2bfloat16(v.w);
                __nv_bfloat16 l0 = __float2bfloat16(v.x - __bfloat162float(h0));
                __nv_bfloat16 l1 = __float2bfloat16(v.y - __bfloat162float(h1));
                __nv_bfloat16 l2 = __float2bfloat16(v.z - __bfloat162float(h2));
                __nv_bfloat16 l3 = __float2bfloat16(v.w - __bfloat162float(h3));
                dhi[q * 2]     = __nv_bfloat162{h0, h1};
                dhi[q * 2 + 1] = __nv_bfloat162{h2, h3};
                dlo[q * 2]     = __nv_bfloat162{l0, l1};
                dlo[q * 2 + 1] = __nv_bfloat162{l2, l3};
            }
        }
        {
            const uint4* shi = (const uint4*)(g_wT_hi + (n0 + srow) * H_DIM + k0 + sc0);
            const uint4* slo = (const uint4*)(g_wT_lo + (n0 + srow) * H_DIM + k0 + sc0);
            uint4* dhi = (uint4*)(sm + SW_HI + srow * LDA_B + sc0 * 2);
            uint4* dlo = (uint4*)(sm + SW_LO + srow * LDA_B + sc0 * 2);
#pragma unroll
            for (int q = 0; q < 4; ++q) { dhi[q] = shi[q]; dlo[q] = slo[q]; }
        }
        __syncthreads();

#pragma unroll
        for (int kk = 0; kk < 4; ++kk) {
            const int kb = kk * 16;
            uint32_t ahi[2][4], alo[2][4], bfr[8][2];

#pragma unroll
            for (int mt = 0; mt < 2; ++mt) {
                uint32_t ra = (wm + mt * 16 + a_row) * LDA_B + (kb + a_c8) * 2;
                ldsm_x4(ahi[mt], smb + SA_HI + ra);
                ldsm_x4(alo[mt], smb + SA_LO + ra);
            }
#pragma unroll
            for (int ntp = 0; ntp < 4; ++ntp) {
                uint32_t rb = (wn + ntp * 16 + b_nof) * LDA_B + (kb + b_kof) * 2;
                uint32_t r[4];
                ldsm_x4(r, smb + SW_HI + rb);
                bfr[ntp * 2][0] = r[0];  bfr[ntp * 2][1] = r[1];
                bfr[ntp * 2 + 1][0] = r[2];  bfr[ntp * 2 + 1][1] = r[3];
            }
#pragma unroll
            for (int mt = 0; mt < 2; ++mt)
#pragma unroll
                for (int nt = 0; nt < 8; ++nt) {
                    mma_bf16(d[mt][nt], ahi[mt], bfr[nt]);
                    mma_bf16(d[mt][nt], alo[mt], bfr[nt]);
                }
#pragma unroll
            for (int ntp = 0; ntp < 4; ++ntp) {
                uint32_t rb = (wn + ntp * 16 + b_nof) * LDA_B + (kb + b_kof) * 2;
                uint32_t r[4];
                ldsm_x4(r, smb + SW_LO + rb);
                bfr[ntp * 2][0] = r[0];  bfr[ntp * 2][1] = r[1];
                bfr[ntp * 2 + 1][0] = r[2];  bfr[ntp * 2 + 1][1] = r[3];
            }
#pragma unroll
            for (int mt = 0; mt < 2; ++mt)
#pragma unroll
                for (int nt = 0; nt < 8; ++nt)
                    mma_bf16(d[mt][nt], ahi[mt], bfr[nt]);
        }
    }

    const float* sbias = (const float*)(sm + SBIAS);
    const int g  = lane >> 2;
    const int tc = lane & 3;
#pragma unroll
    for (int mt = 0; mt < 2; ++mt) {
        long r = m0 + wm + mt * 16 + g;
#pragma unroll
        for (int nt = 0; nt < 8; ++nt) {
            int cn = wn + nt * 8 + tc * 2;
            float b0 = sbias[cn], b1 = sbias[cn + 1];
            *(float2*)&g_xw[r * H_DIM + n0 + cn] =
                make_float2(d[mt][nt][0] + b0, d[mt][nt][1] + b1);
            *(float2*)&g_xw[(r + 8) * H_DIM + n0 + cn] =
                make_float2(d[mt][nt][2] + b0, d[mt][nt][3] + b1);
        }
    }
}

// ---------------------------------------------------------------------------
// Scan. 128 CTAs x 512 threads, 2 batch rows per CTA. f32x2 everywhere.
// DENSE-PLANE smem layout: each k-row of weights (128 colpairs = 1024 B) is
// stored as plane A (every thread's colpairs {0,1}; lane p8 at byte p8*16)
// followed by plane B (colpairs {2,3}). All weight LDS.128 and partial
// STS.128 are then fully dense (4 wavefronts each, zero waste).
// ---------------------------------------------------------------------------
#define KG 16
#define K_PER 16
#define REG_K 8
#define SMEM_K 8
#define SCAN_THREADS 512

#define WSM_U64 (KG * SMEM_K * 128)
#define SCAN_SMEM_U64 (WSM_U64 + 256 + 256 + KG * 128 * 2)
#define SCAN_SMEM_BYTES (SCAN_SMEM_U64 * 8)

__global__ __launch_bounds__(SCAN_THREADS, 1) void scan_kernel(
    const float* __restrict__ xw,
    const float* __restrict__ wh,
    float* __restrict__ out)
{
    extern __shared__ __align__(1024) u64 smu[];
    u64* wsm = smu;
    u64* hd0 = smu + WSM_U64;
    u64* hd1 = hd0 + 256;
    u64* sp0 = hd1 + 256;
    u64* sp1 = sp0 + KG * 128;

    const int tid = threadIdx.x;
    const int kg  = tid >> 5;
    const int p8  = tid & 31;
    const int r0  = blockIdx.x * 2;

    const u64* whd = (const u64*)wh;

    // stage smem half of wh in dense-plane layout:
    //   u64 dst within a k-row: plane=(cp&3)>>1 -> plane*64 + (cp>>2)*2 + (cp&1)
    for (int e = tid; e < WSM_U64; e += SCAN_THREADS) {
        int kgs = e >> 10;
        int kk  = (e >> 7) & 7;
        int cpx = e & 127;
        int dst = (e & ~127) + ((cpx & 3) >> 1) * 64 + (cpx >> 2) * 2 + (cpx & 1);
        wsm[dst] = whd[(kgs * K_PER + REG_K + kk) * 128 + cpx];
    }
    if (tid < 256) { hd0[tid] = 0ull; hd1[tid] = 0ull; }

    u64 wr[REG_K][4];
    const int cpb = p8 * 4;
    const int kb  = kg * K_PER;
#pragma unroll
    for (int kk = 0; kk < REG_K; ++kk)
#pragma unroll
        for (int ci = 0; ci < 4; ++ci)
            wr[kk][ci] = whd[(kb + kk) * 128 + cpb + ci];
    __syncthreads();

    const int rr = tid >> 7;
    const int cp = tid & 127;
    const u64* xwrow = (tid < 256)
        ? (const u64*)xw + ((long)(r0 + rr) * T_DIM) * 128 + cp
        : (const u64*)xw;

    // dense-plane pointers (lane p8 at u64 offset p8*2 within each plane)
    const u64* wsmA = wsm + kg * (SMEM_K * 128) + p8 * 2;        // plane A
    const u64* wsmB = wsmA + 64;                                  // plane B
    const u64* hd0_t = hd0 + kb;
    const u64* hd1_t = hd1 + kb;
    ulonglong2* spA0 = (ulonglong2*)(sp0 + kg * 128 + p8 * 2);
    ulonglong2* spB0 = (ulonglong2*)(sp0 + kg * 128 + 64 + p8 * 2);
    ulonglong2* spA1 = (ulonglong2*)(sp1 + kg * 128 + p8 * 2);
    ulonglong2* spB1 = (ulonglong2*)(sp1 + kg * 128 + 64 + p8 * 2);
    // reduction offset for colpair cp in dense-plane layout
    const int rdoff = ((cp & 3) >> 1) * 64 + (cp >> 2) * 2 + (cp & 1);
    const u64* sprd = (rr == 0) ? sp0 : sp1;
    u64* hdw = (rr == 0) ? hd0 : hd1;

#pragma unroll 1
    for (int t = 0; t < T_DIM; ++t) {
        u64 xv = 0ull;
        if (tid < 256) xv = xwrow[(long)t * 128];

        u64 a00 = 0, a01 = 0, a02 = 0, a03 = 0;
        u64 a10 = 0, a11 = 0, a12 = 0, a13 = 0;

#pragma unroll
        for (int kk = 0; kk < REG_K; kk += 2) {
            ulonglong2 h0p = *(const ulonglong2*)&hd0_t[kk];
            ulonglong2 h1p = *(const ulonglong2*)&hd1_t[kk];
            a00 = f2fma(h0p.x, wr[kk][0], a00);
            a01 = f2fma(h0p.x, wr[kk][1], a01);
            a02 = f2fma(h0p.x, wr[kk][2], a02);
            a03 = f2fma(h0p.x, wr[kk][3], a03);
            a10 = f2fma(h1p.x, wr[kk][0], a10);
            a11 = f2fma(h1p.x, wr[kk][1], a11);
            a12 = f2fma(h1p.x, wr[kk][2], a12);
            a13 = f2fma(h1p.x, wr[kk][3], a13);
            a00 = f2fma(h0p.y, wr[kk + 1][0], a00);
            a01 = f2fma(h0p.y, wr[kk + 1][1], a01);
            a02 = f2fma(h0p.y, wr[kk + 1][2], a02);
            a03 = f2fma(h0p.y, wr[kk + 1][3], a03);
            a10 = f2fma(h1p.y, wr[kk + 1][0], a10);
            a11 = f2fma(h1p.y, wr[kk + 1][1], a11);
            a12 = f2fma(h1p.y, wr[kk + 1][2], a12);
            a13 = f2fma(h1p.y, wr[kk + 1][3], a13);
        }
#pragma unroll
        for (int kk = 0; kk < SMEM_K; kk += 2) {
            ulonglong2 h0p = *(const ulonglong2*)&hd0_t[REG_K + kk];
            ulonglong2 h1p = *(const ulonglong2*)&hd1_t[REG_K + kk];
            ulonglong2 wa0 = *(const ulonglong2*)&wsmA[kk * 128];
            ulonglong2 wb0 = *(const ulonglong2*)&wsmB[kk * 128];
            ulonglong2 wa1 = *(const ulonglong2*)&wsmA[(kk + 1) * 128];
            ulonglong2 wb1 = *(const ulonglong2*)&wsmB[(kk + 1) * 128];
            a00 = f2fma(h0p.x, wa0.x, a00);
            a01 = f2fma(h0p.x, wa0.y, a01);
            a02 = f2fma(h0p.x, wb0.x, a02);
            a03 = f2fma(h0p.x, wb0.y, a03);
            a10 = f2fma(h1p.x, wa0.x, a10);
            a11 = f2fma(h1p.x, wa0.y, a11);
            a12 = f2fma(h1p.x, wb0.x, a12);
            a13 = f2fma(h1p.x, wb0.y, a13);
            a00 = f2fma(h0p.y, wa1.x, a00);
            a01 = f2fma(h0p.y, wa1.y, a01);
            a02 = f2fma(h0p.y, wb1.x, a02);
            a03 = f2fma(h0p.y, wb1.y, a03);
            a10 = f2fma(h1p.y, wa1.x, a10);
            a11 = f2fma(h1p.y, wa1.y, a11);
            a12 = f2fma(h1p.y, wb1.x, a12);
            a13 = f2fma(h1p.y, wb1.y, a13);
        }

        // dense partial stores (plane layout)
        spA0[0] = make_ulonglong2(a00, a01);
        spB0[0] = make_ulonglong2(a02, a03);
        spA1[0] = make_ulonglong2(a10, a11);
        spB1[0] = make_ulonglong2(a12, a13);
        __syncthreads();

        if (tid < 256) {
            u64 s = sprd[rdoff];
#pragma unroll
            for (int g = 1; g < KG; ++g)
                s = f2add(s, sprd[g * 128 + rdoff]);
            s = f2add(s, xv);
            float2 sv = upk(s);
            float v0 = tanhf(sv.x);
            float v1 = tanhf(sv.y);
            *(ulonglong2*)&hdw[2 * cp] = make_ulonglong2(dupf(v0), dupf(v1));
            if (t == T_DIM - 1)
                *(float2*)&out[(long)(r0 + rr) * H_DIM + 2 * cp] =
                    make_float2(v0, v1);
        }
        __syncthreads();
    }
}

// ---------------------------------------------------------------------------
extern "C" void kernel_launch(void* const* d_in, const int* in_sizes, int n_in,
                              void* d_out, int out_size)
{
    const float* x    = (const float*)d_in[0];
    const float* wx   = (const float*)d_in[1];
    const float* wh   = (const float*)d_in[2];
    const float* bias = (const float*)d_in[3];
    float* out = (float*)d_out;

    float* xw;
    cudaGetSymbolAddress((void**)&xw, g_xw);

    prep_kernel<<<H_DIM, H_DIM>>>(wx);

    cudaFuncSetAttribute(proj_kernel,
                         cudaFuncAttributeMaxDynamicSharedMemorySize, PS_TOTAL);
    dim3 pgrid(H_DIM / PN, M_TOTAL / PM);   // (2, 4096)
    proj_kernel<<<pgrid, 256, PS_TOTAL>>>(x, bias);

    cudaFuncSetAttribute(scan_kernel,
                         cudaFuncAttributeMaxDynamicSharedMemorySize,
                         SCAN_SMEM_BYTES);
    scan_kernel<<<B_DIM / 2, SCAN_THREADS, SCAN_SMEM_BYTES>>>(xw, wh, out);
}